// round 1
// baseline (speedup 1.0000x reference)
#include <cuda_runtime.h>
#include <cstdint>
#include <cstdio>

#define Bz   512
#define Wz   50
#define Tz   50
#define Hz   1024
#define Vz   1024
#define MVz  64
#define Lz   30
#define H4z  4096
#define SOSI 0
#define EOSI 1

// ---------------- scratch (device globals; no allocations allowed) ----------
__device__ float g_g[Bz * H4z];            // gate pre-activations (8 MB)
__device__ float g_h[Bz * Hz];             // recurrent h
__device__ float g_c[Bz * Hz];             // recurrent c
__device__ float g_r[Bz * Hz];             // attention-pooled encoder input
__device__ float g_aw[Bz * Wz];            // attention weights
__device__ float g_msg[Lz * Bz * MVz];     // generated message probs
__device__ float g_mmask[Lz * Bz];         // message mask per step
__device__ float g_m[Bz];                  // running mask
__device__ float g_hb_enc[H4z];            // set_h0 @ set_Whh^T  (constant vec)
__device__ float g_xb_gen[H4z];            // gen_x0 @ gen_Wih^T  (constant vec)
__device__ float g_s0;                     // set_h0 . attn_w[:H] (scalar)
__device__ float g_decin[(size_t)Tz * Bz * Hz];  // gathered decoder inputs (~105 MB)

__device__ __forceinline__ float sigm(float x) { return 1.f / (1.f + expf(-x)); }

// ---------------- generic warp-per-row vec @ mat^T -------------------------
// y[j] = sum_k x[k] * Wt[j*K + k]
__global__ void vecmat_kernel(const float* __restrict__ x, const float* __restrict__ Wt,
                              float* __restrict__ y, int N, int K) {
    int j = blockIdx.x * (blockDim.x / 32) + (threadIdx.x >> 5);
    int lane = threadIdx.x & 31;
    if (j >= N) return;
    const float* w = Wt + (size_t)j * K;
    float s = 0.f;
    for (int k = lane; k < K; k += 32) s += x[k] * w[k];
    #pragma unroll
    for (int o = 16; o; o >>= 1) s += __shfl_xor_sync(0xffffffffu, s, o);
    if (lane == 0) y[j] = s;
}

// ---------------- attention weights: aw[b,w] = sig(emb[idx].attn_w2 + s0 + b) * mask
__global__ void attn_aw_kernel(const int* __restrict__ ivar, const float* __restrict__ mask,
                               const float* __restrict__ emb, const float* __restrict__ attw,
                               const float* __restrict__ attb) {
    int p = blockIdx.x * (blockDim.x / 32) + (threadIdx.x >> 5);
    if (p >= Bz * Wz) return;
    int lane = threadIdx.x & 31;
    int b = p / Wz, w = p % Wz;
    const float* e  = emb + (size_t)ivar[p] * Hz;
    const float* wv = attw + Hz;   // second half applies to emb_in
    float s = 0.f;
    for (int k = lane; k < Hz; k += 32) s += e[k] * wv[k];
    #pragma unroll
    for (int o = 16; o; o >>= 1) s += __shfl_xor_sync(0xffffffffu, s, o);
    if (lane == 0) {
        float v = sigm(s + g_s0 + attb[0]);
        g_aw[p] = v * mask[w * Bz + b];
    }
}

// ---------------- r[b,:] = sum_w aw[b,w] * emb[idx[b,w],:]  -----------------
__global__ void attn_r_kernel(const int* __restrict__ ivar, const float* __restrict__ emb) {
    int b  = blockIdx.x;
    int h0 = threadIdx.x * 4;                         // 256 threads * 4 = 1024
    float a0 = 0.f, a1 = 0.f, a2 = 0.f, a3 = 0.f;
    for (int w = 0; w < Wz; ++w) {
        float a = g_aw[b * Wz + w];
        float4 e = *(const float4*)(emb + (size_t)ivar[b * Wz + w] * Hz + h0);
        a0 += a * e.x; a1 += a * e.y; a2 += a * e.z; a3 += a * e.w;
    }
    *(float4*)(g_r + (size_t)b * Hz + h0) = make_float4(a0, a1, a2, a3);
}

// ---------------- broadcast (1,H) row into (B,H) buffer ---------------------
// which: 0 -> g_h, 1 -> g_c
__global__ void bcast_BH_kernel(const float* __restrict__ src, int which) {
    int i = blockIdx.x * blockDim.x + threadIdx.x;
    if (i >= Bz * Hz) return;
    float v = src[i % Hz];
    if (which == 0) g_h[i] = v; else g_c[i] = v;
}

__global__ void init_m_kernel() {
    int i = blockIdx.x * blockDim.x + threadIdx.x;
    if (i < Bz) g_m[i] = 1.f;
}

// ---------------- decoder input gather --------------------------------------
__global__ void dec_gather_kernel(const int* __restrict__ tvar, const float* __restrict__ emb) {
    size_t i = (size_t)blockIdx.x * blockDim.x + threadIdx.x;
    if (i >= (size_t)Tz * Bz * Hz) return;
    int hi = (int)(i % Hz);
    size_t bt = i / Hz;
    int b = (int)(bt % Bz);
    int t = (int)(bt / Bz);
    int row = (t == 0) ? SOSI : tvar[(t - 1) * Bz + b];
    g_decin[i] = emb[(size_t)row * Hz + hi];
}

// ---------------- dual-source SGEMM: C = A1@W1^T + A2@W2^T (+bias) ----------
// A row-major M x K, W row-major N x K. Fixed M=512. N, K multiples of tile.
template <int BM, int BN, int TM, int TN>
__global__ __launch_bounds__(256) void sgemm_dual(
    const float* __restrict__ A1, const float* __restrict__ W1, int K1,
    const float* __restrict__ A2, const float* __restrict__ W2, int K2,
    const float* __restrict__ bias, float* __restrict__ C, int Ntot) {
    constexpr int BK = 16;
    constexpr int THREADS = (BM / TM) * (BN / TN);
    static_assert(THREADS == 256, "block must be 256 threads");
    __shared__ float As[BK][BM];
    __shared__ float Bs[BK][BN];

    const int tid = threadIdx.x;
    const int tx = tid % (BN / TN);
    const int ty = tid / (BN / TN);
    const int m0 = blockIdx.y * BM;
    const int n0 = blockIdx.x * BN;

    float acc[TM][TN] = {};

    #pragma unroll
    for (int pass = 0; pass < 2; ++pass) {
        const float* A = pass ? A2 : A1;
        const float* Wm = pass ? W2 : W1;
        const int K = pass ? K2 : K1;
        if (A == nullptr) continue;
        for (int kk = 0; kk < K; kk += BK) {
            __syncthreads();
            // load A tile (BM x BK) as float4
            #pragma unroll
            for (int e = 0; e < BM * BK / (THREADS * 4); ++e) {
                int idx = tid + e * THREADS;
                int r = idx / (BK / 4);
                int c4 = idx % (BK / 4);
                float4 v = *(const float4*)(A + (size_t)(m0 + r) * K + kk + c4 * 4);
                As[c4 * 4 + 0][r] = v.x; As[c4 * 4 + 1][r] = v.y;
                As[c4 * 4 + 2][r] = v.z; As[c4 * 4 + 3][r] = v.w;
            }
            // load W tile (BN x BK) as float4
            #pragma unroll
            for (int e = 0; e < BN * BK / (THREADS * 4); ++e) {
                int idx = tid + e * THREADS;
                int r = idx / (BK / 4);
                int c4 = idx % (BK / 4);
                float4 v = *(const float4*)(Wm + (size_t)(n0 + r) * K + kk + c4 * 4);
                Bs[c4 * 4 + 0][r] = v.x; Bs[c4 * 4 + 1][r] = v.y;
                Bs[c4 * 4 + 2][r] = v.z; Bs[c4 * 4 + 3][r] = v.w;
            }
            __syncthreads();
            #pragma unroll
            for (int k = 0; k < BK; ++k) {
                float ra[TM], rb[TN];
                #pragma unroll
                for (int i = 0; i < TM; ++i) ra[i] = As[k][ty * TM + i];
                #pragma unroll
                for (int j = 0; j < TN; ++j) rb[j] = Bs[k][tx * TN + j];
                #pragma unroll
                for (int i = 0; i < TM; ++i)
                    #pragma unroll
                    for (int j = 0; j < TN; ++j) acc[i][j] += ra[i] * rb[j];
            }
        }
    }

    #pragma unroll
    for (int i = 0; i < TM; ++i) {
        int m = m0 + ty * TM + i;
        #pragma unroll
        for (int j = 0; j < TN; ++j) {
            int n = n0 + tx * TN + j;
            float v = acc[i][j];
            if (bias) v += bias[n];
            C[(size_t)m * Ntot + n] = v;
        }
    }
}

// ---------------- fused LSTM gates (reads g_g, updates g_h/g_c in place) ----
__global__ void lstm_gate_kernel(const float* __restrict__ bih, const float* __restrict__ bhh,
                                 const float* __restrict__ extra, const float* __restrict__ mask) {
    int i = blockIdx.x * blockDim.x + threadIdx.x;
    if (i >= Bz * Hz) return;
    int b = i / Hz, hi = i % Hz;
    const float* gr = g_g + (size_t)b * H4z;
    float ei = extra ? extra[hi]          : 0.f;
    float ef = extra ? extra[Hz + hi]     : 0.f;
    float eg = extra ? extra[2 * Hz + hi] : 0.f;
    float eo = extra ? extra[3 * Hz + hi] : 0.f;
    float gi = gr[hi]           + bih[hi]           + bhh[hi]           + ei;
    float gf = gr[Hz + hi]      + bih[Hz + hi]      + bhh[Hz + hi]      + ef;
    float gg = gr[2 * Hz + hi]  + bih[2 * Hz + hi]  + bhh[2 * Hz + hi]  + eg;
    float go = gr[3 * Hz + hi]  + bih[3 * Hz + hi]  + bhh[3 * Hz + hi]  + eo;
    float cp = g_c[i], hp = g_h[i];
    float cn = sigm(gf) * cp + sigm(gi) * tanhf(gg);
    float hn = sigm(go) * tanhf(cn);
    if (mask) {
        float mt = mask[b];
        hn = mt * hn + (1.f - mt) * hp;
        cn = mt * cn + (1.f - mt) * cp;
    }
    g_h[i] = hn;
    g_c[i] = cn;
}

// ---------------- gen output: softmax(h @ outW^T + b), message + mask -------
__global__ void gen_out_kernel(const float* __restrict__ outW, const float* __restrict__ outb,
                               int t) {
    int b = blockIdx.x;
    int tid = threadIdx.x;                 // 256 threads = 8 warps
    int warp = tid >> 5, lane = tid & 31;
    __shared__ float logits[MVz];
    __shared__ float red[2];
    const float* hrow = g_h + (size_t)b * Hz;
    for (int j = warp; j < MVz; j += 8) {
        const float* wrow = outW + (size_t)j * Hz;
        float s = 0.f;
        for (int k = lane; k < Hz; k += 32) s += hrow[k] * wrow[k];
        #pragma unroll
        for (int o = 16; o; o >>= 1) s += __shfl_xor_sync(0xffffffffu, s, o);
        if (lane == 0) logits[j] = s + outb[j];
    }
    __syncthreads();
    if (tid < 32) {
        float v1 = logits[tid], v2 = logits[tid + 32];
        float mx = fmaxf(v1, v2);
        #pragma unroll
        for (int o = 16; o; o >>= 1) mx = fmaxf(mx, __shfl_xor_sync(0xffffffffu, mx, o));
        float s = expf(v1 - mx) + expf(v2 - mx);
        #pragma unroll
        for (int o = 16; o; o >>= 1) s += __shfl_xor_sync(0xffffffffu, s, o);
        if (tid == 0) { red[0] = mx; red[1] = s; }
    }
    __syncthreads();
    if (tid < MVz) {
        float p = expf(logits[tid] - red[0]) / red[1];
        g_msg[((size_t)t * Bz + b) * MVz + tid] = p;
        if (tid == EOSI) {
            g_mmask[t * Bz + b] = g_m[b];       // mask BEFORE update (scan semantics)
            g_m[b] = g_m[b] * (1.f - p);
        }
    }
}

// ---------------- host driver ------------------------------------------------
extern "C" void kernel_launch(void* const* d_in, const int* in_sizes, int n_in,
                              void* d_out, int out_size) {
    // target_max_len may or may not be surfaced as a tiny input at slot 3
    int s = (in_sizes[3] <= 16) ? 0 : -1;

    const int*   input_var  = (const int*)  d_in[0];
    const float* input_mask = (const float*)d_in[1];
    const int*   target_var = (const int*)  d_in[2];
    const float* emb      = (const float*)d_in[4 + s];
    const float* attn_w   = (const float*)d_in[5 + s];
    const float* attn_b   = (const float*)d_in[6 + s];
    const float* set_Wih  = (const float*)d_in[7 + s];
    const float* set_Whh  = (const float*)d_in[8 + s];
    const float* set_bih  = (const float*)d_in[9 + s];
    const float* set_bhh  = (const float*)d_in[10 + s];
    const float* set_h0   = (const float*)d_in[11 + s];
    const float* set_c0   = (const float*)d_in[12 + s];
    const float* gen_x0   = (const float*)d_in[13 + s];
    const float* gen_Wih  = (const float*)d_in[14 + s];
    const float* gen_Whh  = (const float*)d_in[15 + s];
    const float* gen_bih  = (const float*)d_in[16 + s];
    const float* gen_bhh  = (const float*)d_in[17 + s];
    const float* gen_outW = (const float*)d_in[18 + s];
    const float* gen_outb = (const float*)d_in[19 + s];
    const float* menc_Wih = (const float*)d_in[20 + s];
    const float* menc_Whh = (const float*)d_in[21 + s];
    const float* menc_bih = (const float*)d_in[22 + s];
    const float* menc_bhh = (const float*)d_in[23 + s];
    const float* menc_h0  = (const float*)d_in[24 + s];
    const float* menc_c0  = (const float*)d_in[25 + s];
    const float* dec_Wih  = (const float*)d_in[26 + s];
    const float* dec_Whh  = (const float*)d_in[27 + s];
    const float* dec_bih  = (const float*)d_in[28 + s];
    const float* dec_bhh  = (const float*)d_in[29 + s];
    const float* dec_outW = (const float*)d_in[30 + s];
    const float* dec_outb = (const float*)d_in[31 + s];
    float* out = (float*)d_out;

    float *p_g, *p_h, *p_msg, *p_hb, *p_xb, *p_s0, *p_decin, *p_mmask, *p_r;
    cudaGetSymbolAddress((void**)&p_g,     g_g);
    cudaGetSymbolAddress((void**)&p_h,     g_h);
    cudaGetSymbolAddress((void**)&p_msg,   g_msg);
    cudaGetSymbolAddress((void**)&p_hb,    g_hb_enc);
    cudaGetSymbolAddress((void**)&p_xb,    g_xb_gen);
    cudaGetSymbolAddress((void**)&p_s0,    g_s0);
    cudaGetSymbolAddress((void**)&p_decin, g_decin);
    cudaGetSymbolAddress((void**)&p_mmask, g_mmask);
    cudaGetSymbolAddress((void**)&p_r,     g_r);

    const dim3 gBig(H4z / 128, Bz / 128);   // (32,4) for N=4096 GEMMs
    const dim3 gOut(Vz / 64,  Bz / 64);     // (16,8) for output projection
    const int GATE_B = (Bz * Hz + 255) / 256;

    // ---- precompute ----
    vecmat_kernel<<<1, 32>>>(set_h0, attn_w, p_s0, 1, Hz);
    vecmat_kernel<<<H4z / 8, 256>>>(set_h0, set_Whh, p_hb, H4z, Hz);
    vecmat_kernel<<<H4z / 8, 256>>>(gen_x0, gen_Wih, p_xb, H4z, MVz);
    attn_aw_kernel<<<(Bz * Wz + 7) / 8, 256>>>(input_var, input_mask, emb, attn_w, attn_b);
    attn_r_kernel<<<Bz, 256>>>(input_var, emb);
    dec_gather_kernel<<<(int)(((size_t)Tz * Bz * Hz + 255) / 256), 256>>>(target_var, emb);
    init_m_kernel<<<2, 256>>>();

    // ---- set encoder (one step, h0/c0 broadcast; h0@Whh folded into extra) ----
    bcast_BH_kernel<<<GATE_B, 256>>>(set_h0, 0);
    bcast_BH_kernel<<<GATE_B, 256>>>(set_c0, 1);
    sgemm_dual<128, 128, 8, 8><<<gBig, 256>>>(p_r, set_Wih, Hz,
                                              nullptr, nullptr, 0,
                                              nullptr, p_g, H4z);
    lstm_gate_kernel<<<GATE_B, 256>>>(set_bih, set_bhh, p_hb, nullptr);

    // ---- generator loop (x is constant zero-ish vector: folded into xb_gen) ----
    for (int t = 0; t < Lz; ++t) {
        sgemm_dual<128, 128, 8, 8><<<gBig, 256>>>(p_h, gen_Whh, Hz,
                                                  nullptr, nullptr, 0,
                                                  nullptr, p_g, H4z);
        lstm_gate_kernel<<<GATE_B, 256>>>(gen_bih, gen_bhh, p_xb, nullptr);
        gen_out_kernel<<<Bz, 256>>>(gen_outW, gen_outb, t);
    }

    // ---- message encoder loop ----
    bcast_BH_kernel<<<GATE_B, 256>>>(menc_h0, 0);
    bcast_BH_kernel<<<GATE_B, 256>>>(menc_c0, 1);
    for (int t = 0; t < Lz; ++t) {
        sgemm_dual<128, 128, 8, 8><<<gBig, 256>>>(p_msg + (size_t)t * Bz * MVz, menc_Wih, MVz,
                                                  p_h, menc_Whh, Hz,
                                                  nullptr, p_g, H4z);
        lstm_gate_kernel<<<GATE_B, 256>>>(menc_bih, menc_bhh, nullptr, p_mmask + (size_t)t * Bz);
    }

    // ---- decoder loop ----
    for (int t = 0; t < Tz; ++t) {
        sgemm_dual<128, 128, 8, 8><<<gBig, 256>>>(p_decin + (size_t)t * Bz * Hz, dec_Wih, Hz,
                                                  p_h, dec_Whh, Hz,
                                                  nullptr, p_g, H4z);
        lstm_gate_kernel<<<GATE_B, 256>>>(dec_bih, dec_bhh, nullptr, nullptr);
        sgemm_dual<64, 64, 4, 4><<<gOut, 256>>>(p_h, dec_outW, Hz,
                                                nullptr, nullptr, 0,
                                                dec_outb, out + (size_t)t * Bz * Vz, Vz);
    }
    (void)n_in; (void)out_size;
}

// round 4
// speedup vs baseline: 1.2838x; 1.2838x over previous
#include <cuda_runtime.h>
#include <cuda_bf16.h>
#include <cstdint>
#include <cstdio>

#define Bz   512
#define Wz   50
#define Tz   50
#define Hz   1024
#define Vz   1024
#define MVz  64
#define Lz   30
#define H4z  4096
#define SOSI 0
#define EOSI 1

// ===================== PTX helpers (base sm_103 ISA only) ===================
__device__ __forceinline__ uint32_t smem_u32(const void* p) {
    uint32_t a;
    asm("{ .reg .u64 t; cvta.to.shared.u64 t, %1; cvt.u32.u64 %0, t; }" : "=r"(a) : "l"(p));
    return a;
}
__device__ __forceinline__ void cp_async16(uint32_t dst, const void* src) {
    asm volatile("cp.async.cg.shared.global [%0], [%1], 16;" :: "r"(dst), "l"(src) : "memory");
}
#define CP_COMMIT() asm volatile("cp.async.commit_group;" ::: "memory")
#define CP_WAIT(n)  asm volatile("cp.async.wait_group %0;" :: "n"(n) : "memory")

__device__ __forceinline__ void ldsm_x4(uint32_t* r, uint32_t addr) {
    asm volatile("ldmatrix.sync.aligned.m8n8.x4.shared.b16 {%0,%1,%2,%3}, [%4];"
                 : "=r"(r[0]), "=r"(r[1]), "=r"(r[2]), "=r"(r[3]) : "r"(addr));
}
__device__ __forceinline__ void mma_bf16(float* c, const uint32_t* a, uint32_t b0, uint32_t b1) {
    asm volatile("mma.sync.aligned.m16n8k16.row.col.f32.bf16.bf16.f32 "
                 "{%0,%1,%2,%3}, {%4,%5,%6,%7}, {%8,%9}, {%0,%1,%2,%3};"
                 : "+f"(c[0]), "+f"(c[1]), "+f"(c[2]), "+f"(c[3])
                 : "r"(a[0]), "r"(a[1]), "r"(a[2]), "r"(a[3]), "r"(b0), "r"(b1));
}

// ===================== scratch (device globals) =============================
__device__ float g_g[Bz * H4z];
__device__ float g_h[Bz * Hz];
__device__ float g_c[Bz * Hz];
__device__ float g_aw[Bz * Wz];
__device__ float g_mmask[Lz * Bz];
__device__ float g_m[Bz];
__device__ float g_hb_enc[H4z];
__device__ float g_xb_gen[H4z];
__device__ float g_s0;

__device__ __nv_bfloat16 g_h_hi[Bz * Hz],  g_h_lo[Bz * Hz];
__device__ __nv_bfloat16 g_r_hi[Bz * Hz],  g_r_lo[Bz * Hz];
__device__ __nv_bfloat16 g_msg_hi[Lz * Bz * MVz], g_msg_lo[Lz * Bz * MVz];
__device__ __nv_bfloat16 g_din_hi[(size_t)Tz * Bz * Hz], g_din_lo[(size_t)Tz * Bz * Hz];

__device__ __nv_bfloat16 w_setWih_hi[H4z * Hz],  w_setWih_lo[H4z * Hz];
__device__ __nv_bfloat16 w_genWhh_hi[H4z * Hz],  w_genWhh_lo[H4z * Hz];
__device__ __nv_bfloat16 w_mencWih_hi[H4z * MVz], w_mencWih_lo[H4z * MVz];
__device__ __nv_bfloat16 w_mencWhh_hi[H4z * Hz], w_mencWhh_lo[H4z * Hz];
__device__ __nv_bfloat16 w_decWih_hi[H4z * Hz],  w_decWih_lo[H4z * Hz];
__device__ __nv_bfloat16 w_decWhh_hi[H4z * Hz],  w_decWhh_lo[H4z * Hz];
__device__ __nv_bfloat16 w_outW_hi[Vz * Hz],     w_outW_lo[Vz * Hz];

__device__ __forceinline__ float sigm(float x) { return 1.f / (1.f + expf(-x)); }
__device__ __forceinline__ void split_bf(float v, __nv_bfloat16& hi, __nv_bfloat16& lo) {
    __nv_bfloat16 h = __float2bfloat16(v);
    hi = h;
    lo = __float2bfloat16(v - __bfloat162float(h));
}

// ===================== small kernels ========================================
__global__ void split_kernel(const float* __restrict__ x, __nv_bfloat16* __restrict__ hi,
                             __nv_bfloat16* __restrict__ lo, int n) {
    int i = blockIdx.x * blockDim.x + threadIdx.x;
    if (i < n) split_bf(x[i], hi[i], lo[i]);
}

__global__ void vecmat_kernel(const float* __restrict__ x, const float* __restrict__ Wt,
                              float* __restrict__ y, int N, int K) {
    int j = blockIdx.x * (blockDim.x / 32) + (threadIdx.x >> 5);
    int lane = threadIdx.x & 31;
    if (j >= N) return;
    const float* w = Wt + (size_t)j * K;
    float s = 0.f;
    for (int k = lane; k < K; k += 32) s += x[k] * w[k];
    #pragma unroll
    for (int o = 16; o; o >>= 1) s += __shfl_xor_sync(0xffffffffu, s, o);
    if (lane == 0) y[j] = s;
}

__global__ void attn_aw_kernel(const int* __restrict__ ivar, const float* __restrict__ mask,
                               const float* __restrict__ emb, const float* __restrict__ attw,
                               const float* __restrict__ attb) {
    int p = blockIdx.x * (blockDim.x / 32) + (threadIdx.x >> 5);
    if (p >= Bz * Wz) return;
    int lane = threadIdx.x & 31;
    int b = p / Wz, w = p % Wz;
    const float* e  = emb + (size_t)ivar[p] * Hz;
    const float* wv = attw + Hz;
    float s = 0.f;
    for (int k = lane; k < Hz; k += 32) s += e[k] * wv[k];
    #pragma unroll
    for (int o = 16; o; o >>= 1) s += __shfl_xor_sync(0xffffffffu, s, o);
    if (lane == 0) {
        float v = sigm(s + g_s0 + attb[0]);
        g_aw[p] = v * mask[w * Bz + b];
    }
}

__global__ void attn_r_kernel(const int* __restrict__ ivar, const float* __restrict__ emb) {
    int b  = blockIdx.x;
    int h0 = threadIdx.x * 4;
    float a0 = 0.f, a1 = 0.f, a2 = 0.f, a3 = 0.f;
    for (int w = 0; w < Wz; ++w) {
        float a = g_aw[b * Wz + w];
        float4 e = *(const float4*)(emb + (size_t)ivar[b * Wz + w] * Hz + h0);
        a0 += a * e.x; a1 += a * e.y; a2 += a * e.z; a3 += a * e.w;
    }
    size_t o = (size_t)b * Hz + h0;
    split_bf(a0, g_r_hi[o + 0], g_r_lo[o + 0]);
    split_bf(a1, g_r_hi[o + 1], g_r_lo[o + 1]);
    split_bf(a2, g_r_hi[o + 2], g_r_lo[o + 2]);
    split_bf(a3, g_r_hi[o + 3], g_r_lo[o + 3]);
}

__global__ void bcast_BH_kernel(const float* __restrict__ src, int which) {
    int i = blockIdx.x * blockDim.x + threadIdx.x;
    if (i >= Bz * Hz) return;
    float v = src[i % Hz];
    if (which == 0) { g_h[i] = v; split_bf(v, g_h_hi[i], g_h_lo[i]); }
    else            g_c[i] = v;
}

__global__ void init_m_kernel() {
    int i = blockIdx.x * blockDim.x + threadIdx.x;
    if (i < Bz) g_m[i] = 1.f;
}

__global__ void dec_gather_kernel(const int* __restrict__ tvar, const float* __restrict__ emb) {
    size_t i = (size_t)blockIdx.x * blockDim.x + threadIdx.x;
    if (i >= (size_t)Tz * Bz * Hz) return;
    int hi = (int)(i % Hz);
    size_t bt = i / Hz;
    int b = (int)(bt % Bz);
    int t = (int)(bt / Bz);
    int row = (t == 0) ? SOSI : tvar[(t - 1) * Bz + b];
    split_bf(emb[(size_t)row * Hz + hi], g_din_hi[i], g_din_lo[i]);
}

__global__ void lstm_gate_kernel(const float* __restrict__ bih, const float* __restrict__ bhh,
                                 const float* __restrict__ extra, const float* __restrict__ mask) {
    int i = blockIdx.x * blockDim.x + threadIdx.x;
    if (i >= Bz * Hz) return;
    int b = i / Hz, hi = i % Hz;
    const float* gr = g_g + (size_t)b * H4z;
    float ei = extra ? extra[hi]          : 0.f;
    float ef = extra ? extra[Hz + hi]     : 0.f;
    float eg = extra ? extra[2 * Hz + hi] : 0.f;
    float eo = extra ? extra[3 * Hz + hi] : 0.f;
    float gi = gr[hi]          + bih[hi]          + bhh[hi]          + ei;
    float gf = gr[Hz + hi]     + bih[Hz + hi]     + bhh[Hz + hi]     + ef;
    float gg = gr[2 * Hz + hi] + bih[2 * Hz + hi] + bhh[2 * Hz + hi] + eg;
    float go = gr[3 * Hz + hi] + bih[3 * Hz + hi] + bhh[3 * Hz + hi] + eo;
    float cp = g_c[i], hp = g_h[i];
    float cn = sigm(gf) * cp + sigm(gi) * tanhf(gg);
    float hn = sigm(go) * tanhf(cn);
    if (mask) {
        float mt = mask[b];
        hn = mt * hn + (1.f - mt) * hp;
        cn = mt * cn + (1.f - mt) * cp;
    }
    g_h[i] = hn;
    g_c[i] = cn;
    split_bf(hn, g_h_hi[i], g_h_lo[i]);
}

__global__ void gen_out_kernel(const float* __restrict__ outW, const float* __restrict__ outb,
                               int t) {
    int b = blockIdx.x;
    int tid = threadIdx.x;
    int warp = tid >> 5, lane = tid & 31;
    __shared__ float logits[MVz];
    __shared__ float red[2];
    const float* hrow = g_h + (size_t)b * Hz;
    for (int j = warp; j < MVz; j += 8) {
        const float* wrow = outW + (size_t)j * Hz;
        float s = 0.f;
        for (int k = lane; k < Hz; k += 32) s += hrow[k] * wrow[k];
        #pragma unroll
        for (int o = 16; o; o >>= 1) s += __shfl_xor_sync(0xffffffffu, s, o);
        if (lane == 0) logits[j] = s + outb[j];
    }
    __syncthreads();
    if (tid < 32) {
        float v1 = logits[tid], v2 = logits[tid + 32];
        float mx = fmaxf(v1, v2);
        #pragma unroll
        for (int o = 16; o; o >>= 1) mx = fmaxf(mx, __shfl_xor_sync(0xffffffffu, mx, o));
        float s = expf(v1 - mx) + expf(v2 - mx);
        #pragma unroll
        for (int o = 16; o; o >>= 1) s += __shfl_xor_sync(0xffffffffu, s, o);
        if (tid == 0) { red[0] = mx; red[1] = s; }
    }
    __syncthreads();
    if (tid < MVz) {
        float p = expf(logits[tid] - red[0]) / red[1];
        size_t o = ((size_t)t * Bz + b) * MVz + tid;
        split_bf(p, g_msg_hi[o], g_msg_lo[o]);
        if (tid == EOSI) {
            g_mmask[t * Bz + b] = g_m[b];
            g_m[b] = g_m[b] * (1.f - p);
        }
    }
}

// ===================== mma.sync bf16 GEMM ===================================
// C[M=512, Ntot] = A1@W1^T + A2@W2^T (+bias). Each fp32 operand supplied as
// bf16 (hi, lo); 3 phases per source: hi*hi, hi*lo, lo*hi, fp32 accum in regs.
// CTA tile 128x128, 8 warps (2x4), warp tile 64x32, K-chunk 64 bf16 (128B rows,
// XOR-swizzled smem), 3-stage cp.async pipeline, ldmatrix fragment loads.

#define TC_SMEM_BYTES (3 * 32768)

__device__ __forceinline__ void load_stage(
    int s, int buf, uint32_t smem_base, int tid, int m0, int n0,
    const __nv_bfloat16* A1h, const __nv_bfloat16* A1l,
    const __nv_bfloat16* W1h, const __nv_bfloat16* W1l, int K1, int S1,
    const __nv_bfloat16* A2h, const __nv_bfloat16* A2l,
    const __nv_bfloat16* W2h, const __nv_bfloat16* W2l, int K2)
{
    const __nv_bfloat16 *A, *W; int K, ph, c;
    if (s < S1) {
        const int cs = K1 >> 6;
        ph = s / cs; c = s - ph * cs;
        A = (ph == 2) ? A1l : A1h;
        W = (ph == 1) ? W1l : W1h;
        K = K1;
    } else {
        const int s2 = s - S1;
        const int cs = K2 >> 6;
        ph = s2 / cs; c = s2 - ph * cs;
        A = (ph == 2) ? A2l : A2h;
        W = (ph == 1) ? W2l : W2h;
        K = K2;
    }
    const int row = tid & 127;
    const bool isW = tid >= 128;
    const char* src = isW ? (const char*)(W + (size_t)(n0 + row) * K + c * 64)
                          : (const char*)(A + (size_t)(m0 + row) * K + c * 64);
    const uint32_t base = smem_base + buf * 32768 + (isW ? 16384 : 0) + row * 128;
    const int sw = row & 7;
    #pragma unroll
    for (int g = 0; g < 8; ++g)
        cp_async16(base + (uint32_t)((g ^ sw) << 4), src + g * 16);
    CP_COMMIT();
}

__global__ __launch_bounds__(256) void tc_gemm(
    const __nv_bfloat16* __restrict__ A1h, const __nv_bfloat16* __restrict__ A1l,
    const __nv_bfloat16* __restrict__ W1h, const __nv_bfloat16* __restrict__ W1l, int K1,
    const __nv_bfloat16* __restrict__ A2h, const __nv_bfloat16* __restrict__ A2l,
    const __nv_bfloat16* __restrict__ W2h, const __nv_bfloat16* __restrict__ W2l, int K2,
    const float* __restrict__ bias, float* __restrict__ C, int Ntot)
{
    extern __shared__ char smem[];
    const uint32_t smem_base = smem_u32(smem);
    const int tid = threadIdx.x;
    const int wid = tid >> 5, lane = tid & 31;
    const int wm = wid & 1, wn = wid >> 1;          // warp tile origin (wm*64, wn*32)
    const int m0 = blockIdx.y * 128;
    const int n0 = blockIdx.x * 128;

    const int S1 = K1 ? 3 * (K1 >> 6) : 0;
    const int S2 = K2 ? 3 * (K2 >> 6) : 0;
    const int S = S1 + S2;

    float acc[4][4][4];
    #pragma unroll
    for (int i = 0; i < 4; ++i)
        #pragma unroll
        for (int j = 0; j < 4; ++j)
            #pragma unroll
            for (int k = 0; k < 4; ++k) acc[i][j][k] = 0.f;

    load_stage(0, 0, smem_base, tid, m0, n0, A1h, A1l, W1h, W1l, K1, S1, A2h, A2l, W2h, W2l, K2);
    if (S > 1)
        load_stage(1, 1, smem_base, tid, m0, n0, A1h, A1l, W1h, W1l, K1, S1, A2h, A2l, W2h, W2l, K2);

    // ldmatrix lane decode (constant across stages)
    const int tsel = lane >> 3;        // 0..3 (8x8 tile select)
    const int trow = lane & 7;

    for (int s = 0; s < S; ++s) {
        const int buf = s % 3;
        if (s + 2 < S) {
            load_stage(s + 2, (s + 2) % 3, smem_base, tid, m0, n0,
                       A1h, A1l, W1h, W1l, K1, S1, A2h, A2l, W2h, W2l, K2);
            CP_WAIT(2);
        } else if (s + 1 < S) {
            CP_WAIT(1);
        } else {
            CP_WAIT(0);
        }
        __syncthreads();

        const uint32_t Ab = smem_base + buf * 32768;
        const uint32_t Wb = Ab + 16384;

        #pragma unroll
        for (int ks = 0; ks < 4; ++ks) {
            uint32_t af[4][4];
            #pragma unroll
            for (int mi = 0; mi < 4; ++mi) {
                const int row = wm * 64 + mi * 16 + (tsel & 1) * 8 + trow;
                const int g   = ks * 2 + (tsel >> 1);
                ldsm_x4(af[mi], Ab + row * 128 + (uint32_t)(((g ^ (row & 7)) << 4)));
            }
            uint32_t bf[2][4];
            #pragma unroll
            for (int np = 0; np < 2; ++np) {
                const int n = wn * 32 + np * 16 + (tsel >> 1) * 8 + trow;
                const int g = ks * 2 + (tsel & 1);
                ldsm_x4(bf[np], Wb + n * 128 + (uint32_t)(((g ^ (n & 7)) << 4)));
            }
            #pragma unroll
            for (int mi = 0; mi < 4; ++mi)
                #pragma unroll
                for (int ni = 0; ni < 4; ++ni)
                    mma_bf16(acc[mi][ni], af[mi], bf[ni >> 1][(ni & 1) * 2],
                             bf[ni >> 1][(ni & 1) * 2 + 1]);
        }
        __syncthreads();
    }

    // epilogue: direct float2 stores
    const int erow = lane >> 2;          // 0..7
    const int ecol = (lane & 3) * 2;     // 0,2,4,6
    #pragma unroll
    for (int mi = 0; mi < 4; ++mi) {
        const int r0 = m0 + wm * 64 + mi * 16 + erow;
        #pragma unroll
        for (int ni = 0; ni < 4; ++ni) {
            const int n = n0 + wn * 32 + ni * 8 + ecol;
            float b0 = 0.f, b1 = 0.f;
            if (bias) { b0 = bias[n]; b1 = bias[n + 1]; }
            float2 v0 = make_float2(acc[mi][ni][0] + b0, acc[mi][ni][1] + b1);
            float2 v1 = make_float2(acc[mi][ni][2] + b0, acc[mi][ni][3] + b1);
            *(float2*)(C + (size_t)r0 * Ntot + n)       = v0;
            *(float2*)(C + (size_t)(r0 + 8) * Ntot + n) = v1;
        }
    }
}

// ===================== host driver ==========================================
extern "C" void kernel_launch(void* const* d_in, const int* in_sizes, int n_in,
                              void* d_out, int out_size) {
    int s = (in_sizes[3] <= 16) ? 0 : -1;

    const int*   input_var  = (const int*)  d_in[0];
    const float* input_mask = (const float*)d_in[1];
    const int*   target_var = (const int*)  d_in[2];
    const float* emb      = (const float*)d_in[4 + s];
    const float* attn_w   = (const float*)d_in[5 + s];
    const float* attn_b   = (const float*)d_in[6 + s];
    const float* set_Wih  = (const float*)d_in[7 + s];
    const float* set_Whh  = (const float*)d_in[8 + s];
    const float* set_bih  = (const float*)d_in[9 + s];
    const float* set_bhh  = (const float*)d_in[10 + s];
    const float* set_h0   = (const float*)d_in[11 + s];
    const float* set_c0   = (const float*)d_in[12 + s];
    const float* gen_x0   = (const float*)d_in[13 + s];
    const float* gen_Wih  = (const float*)d_in[14 + s];
    const float* gen_Whh  = (const float*)d_in[15 + s];
    const float* gen_bih  = (const float*)d_in[16 + s];
    const float* gen_bhh  = (const float*)d_in[17 + s];
    const float* gen_outW = (const float*)d_in[18 + s];
    const float* gen_outb = (const float*)d_in[19 + s];
    const float* menc_Wih = (const float*)d_in[20 + s];
    const float* menc_Whh = (const float*)d_in[21 + s];
    const float* menc_bih = (const float*)d_in[22 + s];
    const float* menc_bhh = (const float*)d_in[23 + s];
    const float* menc_h0  = (const float*)d_in[24 + s];
    const float* menc_c0  = (const float*)d_in[25 + s];
    const float* dec_Wih  = (const float*)d_in[26 + s];
    const float* dec_Whh  = (const float*)d_in[27 + s];
    const float* dec_bih  = (const float*)d_in[28 + s];
    const float* dec_bhh  = (const float*)d_in[29 + s];
    const float* dec_outW = (const float*)d_in[30 + s];
    const float* dec_outb = (const float*)d_in[31 + s];
    float* out = (float*)d_out;

    cudaFuncSetAttribute(tc_gemm, cudaFuncAttributeMaxDynamicSharedMemorySize, TC_SMEM_BYTES);

    float *p_g, *p_hb, *p_xb, *p_s0, *p_mmask;
    cudaGetSymbolAddress((void**)&p_g,     g_g);
    cudaGetSymbolAddress((void**)&p_hb,    g_hb_enc);
    cudaGetSymbolAddress((void**)&p_xb,    g_xb_gen);
    cudaGetSymbolAddress((void**)&p_s0,    g_s0);
    cudaGetSymbolAddress((void**)&p_mmask, g_mmask);

    __nv_bfloat16 *hh, *hl, *rh, *rl, *mh, *ml, *dh, *dl;
    cudaGetSymbolAddress((void**)&hh, g_h_hi);  cudaGetSymbolAddress((void**)&hl, g_h_lo);
    cudaGetSymbolAddress((void**)&rh, g_r_hi);  cudaGetSymbolAddress((void**)&rl, g_r_lo);
    cudaGetSymbolAddress((void**)&mh, g_msg_hi); cudaGetSymbolAddress((void**)&ml, g_msg_lo);
    cudaGetSymbolAddress((void**)&dh, g_din_hi); cudaGetSymbolAddress((void**)&dl, g_din_lo);

    __nv_bfloat16 *sWih_h, *sWih_l, *gWhh_h, *gWhh_l, *mWih_h, *mWih_l,
                  *mWhh_h, *mWhh_l, *dWih_h, *dWih_l, *dWhh_h, *dWhh_l, *oW_h, *oW_l;
    cudaGetSymbolAddress((void**)&sWih_h, w_setWih_hi);  cudaGetSymbolAddress((void**)&sWih_l, w_setWih_lo);
    cudaGetSymbolAddress((void**)&gWhh_h, w_genWhh_hi);  cudaGetSymbolAddress((void**)&gWhh_l, w_genWhh_lo);
    cudaGetSymbolAddress((void**)&mWih_h, w_mencWih_hi); cudaGetSymbolAddress((void**)&mWih_l, w_mencWih_lo);
    cudaGetSymbolAddress((void**)&mWhh_h, w_mencWhh_hi); cudaGetSymbolAddress((void**)&mWhh_l, w_mencWhh_lo);
    cudaGetSymbolAddress((void**)&dWih_h, w_decWih_hi);  cudaGetSymbolAddress((void**)&dWih_l, w_decWih_lo);
    cudaGetSymbolAddress((void**)&dWhh_h, w_decWhh_hi);  cudaGetSymbolAddress((void**)&dWhh_l, w_decWhh_lo);
    cudaGetSymbolAddress((void**)&oW_h,   w_outW_hi);    cudaGetSymbolAddress((void**)&oW_l,   w_outW_lo);

    const dim3 gBig(H4z / 128, Bz / 128);   // (32, 4)
    const dim3 gOut(Vz / 128,  Bz / 128);   // (8, 4)
    const int GATE_B = (Bz * Hz + 255) / 256;
    const int SPLIT_T = 256;

    // ---- weight splits (fp32 -> bf16 hi/lo) ----
    split_kernel<<<(H4z * Hz + SPLIT_T - 1) / SPLIT_T, SPLIT_T>>>(set_Wih,  sWih_h, sWih_l, H4z * Hz);
    split_kernel<<<(H4z * Hz + SPLIT_T - 1) / SPLIT_T, SPLIT_T>>>(gen_Whh,  gWhh_h, gWhh_l, H4z * Hz);
    split_kernel<<<(H4z * MVz + SPLIT_T - 1) / SPLIT_T, SPLIT_T>>>(menc_Wih, mWih_h, mWih_l, H4z * MVz);
    split_kernel<<<(H4z * Hz + SPLIT_T - 1) / SPLIT_T, SPLIT_T>>>(menc_Whh, mWhh_h, mWhh_l, H4z * Hz);
    split_kernel<<<(H4z * Hz + SPLIT_T - 1) / SPLIT_T, SPLIT_T>>>(dec_Wih,  dWih_h, dWih_l, H4z * Hz);
    split_kernel<<<(H4z * Hz + SPLIT_T - 1) / SPLIT_T, SPLIT_T>>>(dec_Whh,  dWhh_h, dWhh_l, H4z * Hz);
    split_kernel<<<(Vz * Hz + SPLIT_T - 1) / SPLIT_T, SPLIT_T>>>(dec_outW, oW_h, oW_l, Vz * Hz);

    // ---- precompute ----
    vecmat_kernel<<<1, 32>>>(set_h0, attn_w, p_s0, 1, Hz);
    vecmat_kernel<<<H4z / 8, 256>>>(set_h0, set_Whh, p_hb, H4z, Hz);
    vecmat_kernel<<<H4z / 8, 256>>>(gen_x0, gen_Wih, p_xb, H4z, MVz);
    attn_aw_kernel<<<(Bz * Wz + 7) / 8, 256>>>(input_var, input_mask, emb, attn_w, attn_b);
    attn_r_kernel<<<Bz, 256>>>(input_var, emb);
    dec_gather_kernel<<<(int)(((size_t)Tz * Bz * Hz + 255) / 256), 256>>>(target_var, emb);
    init_m_kernel<<<2, 256>>>();

    // ---- set encoder ----
    bcast_BH_kernel<<<GATE_B, 256>>>(set_h0, 0);
    bcast_BH_kernel<<<GATE_B, 256>>>(set_c0, 1);
    tc_gemm<<<gBig, 256, TC_SMEM_BYTES>>>(rh, rl, sWih_h, sWih_l, Hz,
                                          nullptr, nullptr, nullptr, nullptr, 0,
                                          nullptr, p_g, H4z);
    lstm_gate_kernel<<<GATE_B, 256>>>(set_bih, set_bhh, p_hb, nullptr);

    // ---- generator loop ----
    for (int t = 0; t < Lz; ++t) {
        tc_gemm<<<gBig, 256, TC_SMEM_BYTES>>>(hh, hl, gWhh_h, gWhh_l, Hz,
                                              nullptr, nullptr, nullptr, nullptr, 0,
                                              nullptr, p_g, H4z);
        lstm_gate_kernel<<<GATE_B, 256>>>(gen_bih, gen_bhh, p_xb, nullptr);
        gen_out_kernel<<<Bz, 256>>>(gen_outW, gen_outb, t);
    }

    // ---- message encoder loop ----
    bcast_BH_kernel<<<GATE_B, 256>>>(menc_h0, 0);
    bcast_BH_kernel<<<GATE_B, 256>>>(menc_c0, 1);
    for (int t = 0; t < Lz; ++t) {
        tc_gemm<<<gBig, 256, TC_SMEM_BYTES>>>(mh + (size_t)t * Bz * MVz, ml + (size_t)t * Bz * MVz,
                                              mWih_h, mWih_l, MVz,
                                              hh, hl, mWhh_h, mWhh_l, Hz,
                                              nullptr, p_g, H4z);
        lstm_gate_kernel<<<GATE_B, 256>>>(menc_bih, menc_bhh, nullptr, p_mmask + (size_t)t * Bz);
    }

    // ---- decoder loop ----
    for (int t = 0; t < Tz; ++t) {
        tc_gemm<<<gBig, 256, TC_SMEM_BYTES>>>(dh + (size_t)t * Bz * Hz, dl + (size_t)t * Bz * Hz,
                                              dWih_h, dWih_l, Hz,
                                              hh, hl, dWhh_h, dWhh_l, Hz,
                                              nullptr, p_g, H4z);
        lstm_gate_kernel<<<GATE_B, 256>>>(dec_bih, dec_bhh, nullptr, nullptr);
        tc_gemm<<<gOut, 256, TC_SMEM_BYTES>>>(hh, hl, oW_h, oW_l, Hz,
                                              nullptr, nullptr, nullptr, nullptr, 0,
                                              dec_outb, out + (size_t)t * Bz * Vz, Vz);
    }
    (void)n_in; (void)out_size;
}

// round 5
// speedup vs baseline: 3.2373x; 2.5217x over previous
#include <cuda_runtime.h>
#include <cuda_bf16.h>
#include <cstdint>
#include <cstdio>

#define Bz   512
#define Wz   50
#define Tz   50
#define Hz   1024
#define Vz   1024
#define MVz  64
#define Lz   30
#define H4z  4096
#define SOSI 0
#define EOSI 1

// ===================== PTX helpers (base sm_103 ISA only) ===================
__device__ __forceinline__ uint32_t smem_u32(const void* p) {
    uint32_t a;
    asm("{ .reg .u64 t; cvta.to.shared.u64 t, %1; cvt.u32.u64 %0, t; }" : "=r"(a) : "l"(p));
    return a;
}
#define MBARRIER_INIT(addr, cnt) \
    asm volatile("mbarrier.init.shared.b64 [%0], %1;" :: "r"((uint32_t)(addr)), "r"((uint32_t)(cnt)) : "memory")
#define MBAR_WAIT(addr, parity) do {                                              \
    uint32_t _mb = (uint32_t)(addr); uint32_t _pp = (uint32_t)(parity);           \
    uint32_t _done;                                                               \
    asm volatile("{\n\t.reg .pred p;\n\t"                                         \
        "mbarrier.try_wait.parity.acquire.cta.shared::cta.b64 p, [%1], %2;\n\t"   \
        "selp.b32 %0, 1, 0, p;\n\t}" : "=r"(_done) : "r"(_mb), "r"(_pp) : "memory"); \
    if (!_done) {                                                                 \
        asm volatile("{\n\t.reg .pred P1;\n\t"                                    \
            "WL_%=:\n\t"                                                          \
            "mbarrier.try_wait.parity.acquire.cta.shared::cta.b64 P1, [%0], %1, 0x989680;\n\t" \
            "@P1 bra.uni WD_%=;\n\t"                                              \
            "bra.uni WL_%=;\n\t"                                                  \
            "WD_%=:\n\t}" :: "r"(_mb), "r"(_pp) : "memory");                      \
    }                                                                             \
} while (0)

__device__ __forceinline__ void bulkcp(uint32_t dst, const void* src, uint32_t mbar) {
    asm volatile("cp.async.bulk.shared::cluster.global.mbarrier::complete_tx::bytes [%0], [%1], %2, [%3];"
        :: "r"(dst), "l"(src), "r"(16384u), "r"(mbar) : "memory");
}
__device__ __forceinline__ void ldsm_x4(uint32_t* r, uint32_t addr) {
    asm volatile("ldmatrix.sync.aligned.m8n8.x4.shared.b16 {%0,%1,%2,%3}, [%4];"
                 : "=r"(r[0]), "=r"(r[1]), "=r"(r[2]), "=r"(r[3]) : "r"(addr));
}
__device__ __forceinline__ void mma_bf16(float* c, const uint32_t* a, uint32_t b0, uint32_t b1) {
    asm volatile("mma.sync.aligned.m16n8k16.row.col.f32.bf16.bf16.f32 "
                 "{%0,%1,%2,%3}, {%4,%5,%6,%7}, {%8,%9}, {%0,%1,%2,%3};"
                 : "+f"(c[0]), "+f"(c[1]), "+f"(c[2]), "+f"(c[3])
                 : "r"(a[0]), "r"(a[1]), "r"(a[2]), "r"(a[3]), "r"(b0), "r"(b1));
}

// ===================== blocked (tile-image) layout ==========================
// A matrix R x K (bf16) is stored as 16KB blocks of 128 rows x 64 cols with the
// ldmatrix XOR swizzle pre-applied, so a block is a verbatim smem tile image.
__device__ __forceinline__ size_t blk_idx(int r, int k, int K) {
    const int rt = r >> 7, kc = k >> 6;
    const int rr = r & 127, kk = k & 63;
    const int gs = (kk >> 3) ^ (rr & 7);
    return ((size_t)(rt * (K >> 6) + kc) << 13) + rr * 64 + gs * 8 + (kk & 7);
}

// ===================== scratch (device globals) =============================
__device__ float g_g[Bz * H4z];
__device__ float g_h[Bz * Hz];
__device__ float g_c[Bz * Hz];
__device__ float g_aw[Bz * Wz];
__device__ float g_mmask[Lz * Bz];
__device__ float g_m[Bz];
__device__ float g_hb_enc[H4z];
__device__ float g_xb_gen[H4z];
__device__ float g_s0;

__device__ __align__(1024) __nv_bfloat16 g_h_hi[Bz * Hz],  g_h_lo[Bz * Hz];
__device__ __align__(1024) __nv_bfloat16 g_r_hi[Bz * Hz],  g_r_lo[Bz * Hz];
__device__ __align__(1024) __nv_bfloat16 g_msg_hi[Lz * Bz * MVz], g_msg_lo[Lz * Bz * MVz];
__device__ __align__(1024) __nv_bfloat16 g_din_hi[(size_t)Tz * Bz * Hz], g_din_lo[(size_t)Tz * Bz * Hz];

__device__ __align__(1024) __nv_bfloat16 w_setWih_hi[H4z * Hz],  w_setWih_lo[H4z * Hz];
__device__ __align__(1024) __nv_bfloat16 w_genWhh_hi[H4z * Hz],  w_genWhh_lo[H4z * Hz];
__device__ __align__(1024) __nv_bfloat16 w_mencWih_hi[H4z * MVz], w_mencWih_lo[H4z * MVz];
__device__ __align__(1024) __nv_bfloat16 w_mencWhh_hi[H4z * Hz], w_mencWhh_lo[H4z * Hz];
__device__ __align__(1024) __nv_bfloat16 w_decWih_hi[H4z * Hz],  w_decWih_lo[H4z * Hz];
__device__ __align__(1024) __nv_bfloat16 w_decWhh_hi[H4z * Hz],  w_decWhh_lo[H4z * Hz];
__device__ __align__(1024) __nv_bfloat16 w_outW_hi[Vz * Hz],     w_outW_lo[Vz * Hz];

__device__ __forceinline__ float sigm(float x) { return 1.f / (1.f + expf(-x)); }
__device__ __forceinline__ void split_bf(float v, __nv_bfloat16& hi, __nv_bfloat16& lo) {
    __nv_bfloat16 h = __float2bfloat16(v);
    hi = h;
    lo = __float2bfloat16(v - __bfloat162float(h));
}

// ===================== small kernels ========================================
__global__ void split_w_blk_kernel(const float* __restrict__ x, __nv_bfloat16* __restrict__ hi,
                                   __nv_bfloat16* __restrict__ lo, int K, int n) {
    int i = blockIdx.x * blockDim.x + threadIdx.x;
    if (i >= n) return;
    size_t bi = blk_idx(i / K, i % K, K);
    split_bf(x[i], hi[bi], lo[bi]);
}

__global__ void vecmat_kernel(const float* __restrict__ x, const float* __restrict__ Wt,
                              float* __restrict__ y, int N, int K) {
    int j = blockIdx.x * (blockDim.x / 32) + (threadIdx.x >> 5);
    int lane = threadIdx.x & 31;
    if (j >= N) return;
    const float* w = Wt + (size_t)j * K;
    float s = 0.f;
    for (int k = lane; k < K; k += 32) s += x[k] * w[k];
    #pragma unroll
    for (int o = 16; o; o >>= 1) s += __shfl_xor_sync(0xffffffffu, s, o);
    if (lane == 0) y[j] = s;
}

__global__ void attn_aw_kernel(const int* __restrict__ ivar, const float* __restrict__ mask,
                               const float* __restrict__ emb, const float* __restrict__ attw,
                               const float* __restrict__ attb) {
    int p = blockIdx.x * (blockDim.x / 32) + (threadIdx.x >> 5);
    if (p >= Bz * Wz) return;
    int lane = threadIdx.x & 31;
    int b = p / Wz, w = p % Wz;
    const float* e  = emb + (size_t)ivar[p] * Hz;
    const float* wv = attw + Hz;
    float s = 0.f;
    for (int k = lane; k < Hz; k += 32) s += e[k] * wv[k];
    #pragma unroll
    for (int o = 16; o; o >>= 1) s += __shfl_xor_sync(0xffffffffu, s, o);
    if (lane == 0) {
        float v = sigm(s + g_s0 + attb[0]);
        g_aw[p] = v * mask[w * Bz + b];
    }
}

__global__ void attn_r_kernel(const int* __restrict__ ivar, const float* __restrict__ emb) {
    int b  = blockIdx.x;
    int h0 = threadIdx.x * 4;
    float a[4] = {0.f, 0.f, 0.f, 0.f};
    for (int w = 0; w < Wz; ++w) {
        float aw = g_aw[b * Wz + w];
        float4 e = *(const float4*)(emb + (size_t)ivar[b * Wz + w] * Hz + h0);
        a[0] += aw * e.x; a[1] += aw * e.y; a[2] += aw * e.z; a[3] += aw * e.w;
    }
    #pragma unroll
    for (int j = 0; j < 4; ++j) {
        size_t bi = blk_idx(b, h0 + j, Hz);
        split_bf(a[j], g_r_hi[bi], g_r_lo[bi]);
    }
}

__global__ void bcast_BH_kernel(const float* __restrict__ src, int which) {
    int i = blockIdx.x * blockDim.x + threadIdx.x;
    if (i >= Bz * Hz) return;
    int b = i / Hz, hi = i % Hz;
    float v = src[hi];
    if (which == 0) {
        g_h[i] = v;
        size_t bi = blk_idx(b, hi, Hz);
        split_bf(v, g_h_hi[bi], g_h_lo[bi]);
    } else g_c[i] = v;
}

__global__ void init_m_kernel() {
    int i = blockIdx.x * blockDim.x + threadIdx.x;
    if (i < Bz) g_m[i] = 1.f;
}

__global__ void dec_gather_kernel(const int* __restrict__ tvar, const float* __restrict__ emb) {
    size_t i = (size_t)blockIdx.x * blockDim.x + threadIdx.x;
    if (i >= (size_t)Tz * Bz * Hz) return;
    int hi = (int)(i % Hz);
    size_t bt = i / Hz;
    int b = (int)(bt % Bz);
    int t = (int)(bt / Bz);
    int row = (t == 0) ? SOSI : tvar[(t - 1) * Bz + b];
    size_t bi = (size_t)t * (Bz * Hz) + blk_idx(b, hi, Hz);
    split_bf(emb[(size_t)row * Hz + hi], g_din_hi[bi], g_din_lo[bi]);
}

__global__ void lstm_gate_kernel(const float* __restrict__ bih, const float* __restrict__ bhh,
                                 const float* __restrict__ extra, const float* __restrict__ mask) {
    int i = blockIdx.x * blockDim.x + threadIdx.x;
    if (i >= Bz * Hz) return;
    int b = i / Hz, hi = i % Hz;
    const float* gr = g_g + (size_t)b * H4z;
    float ei = extra ? extra[hi]          : 0.f;
    float ef = extra ? extra[Hz + hi]     : 0.f;
    float eg = extra ? extra[2 * Hz + hi] : 0.f;
    float eo = extra ? extra[3 * Hz + hi] : 0.f;
    float gi = gr[hi]          + bih[hi]          + bhh[hi]          + ei;
    float gf = gr[Hz + hi]     + bih[Hz + hi]     + bhh[Hz + hi]     + ef;
    float gg = gr[2 * Hz + hi] + bih[2 * Hz + hi] + bhh[2 * Hz + hi] + eg;
    float go = gr[3 * Hz + hi] + bih[3 * Hz + hi] + bhh[3 * Hz + hi] + eo;
    float cp = g_c[i], hp = g_h[i];
    float cn = sigm(gf) * cp + sigm(gi) * tanhf(gg);
    float hn = sigm(go) * tanhf(cn);
    if (mask) {
        float mt = mask[b];
        hn = mt * hn + (1.f - mt) * hp;
        cn = mt * cn + (1.f - mt) * cp;
    }
    g_h[i] = hn;
    g_c[i] = cn;
    size_t bi = blk_idx(b, hi, Hz);
    split_bf(hn, g_h_hi[bi], g_h_lo[bi]);
}

__global__ void gen_out_kernel(const float* __restrict__ outW, const float* __restrict__ outb,
                               int t) {
    int b = blockIdx.x;
    int tid = threadIdx.x;
    int warp = tid >> 5, lane = tid & 31;
    __shared__ float logits[MVz];
    __shared__ float red[2];
    const float* hrow = g_h + (size_t)b * Hz;
    for (int j = warp; j < MVz; j += 8) {
        const float* wrow = outW + (size_t)j * Hz;
        float s = 0.f;
        for (int k = lane; k < Hz; k += 32) s += hrow[k] * wrow[k];
        #pragma unroll
        for (int o = 16; o; o >>= 1) s += __shfl_xor_sync(0xffffffffu, s, o);
        if (lane == 0) logits[j] = s + outb[j];
    }
    __syncthreads();
    if (tid < 32) {
        float v1 = logits[tid], v2 = logits[tid + 32];
        float mx = fmaxf(v1, v2);
        #pragma unroll
        for (int o = 16; o; o >>= 1) mx = fmaxf(mx, __shfl_xor_sync(0xffffffffu, mx, o));
        float s = expf(v1 - mx) + expf(v2 - mx);
        #pragma unroll
        for (int o = 16; o; o >>= 1) s += __shfl_xor_sync(0xffffffffu, s, o);
        if (tid == 0) { red[0] = mx; red[1] = s; }
    }
    __syncthreads();
    if (tid < MVz) {
        float p = expf(logits[tid] - red[0]) / red[1];
        size_t bi = (size_t)t * (Bz * MVz) + blk_idx(b, tid, MVz);
        split_bf(p, g_msg_hi[bi], g_msg_lo[bi]);
        if (tid == EOSI) {
            g_mmask[t * Bz + b] = g_m[b];
            g_m[b] = g_m[b] * (1.f - p);
        }
    }
}

// ===================== bulk-copy mma.sync GEMM ==============================
// C[512, Ntot] = A1@W1^T + A2@W2^T (+bias); operands as blocked bf16 hi/lo.
// Per 64-K stage: one thread bulk-copies 4 tile images (Ah, Al, Wh, Wl, 64KB),
// all warps compute 3 combos (Ah*Wh + Ah*Wl + Al*Wh) with fragment reuse.
// 3-deep pipeline, mbarrier expect_tx completion. CTA 128x128, warp 64x32.

#define STG 65536
#define TC_SMEM_BYTES (1024 + 3 * STG)

__device__ __forceinline__ void issue_stage(
    int s, int buf, uint32_t sb, int mt, int nt,
    const __nv_bfloat16* Ah1, const __nv_bfloat16* Al1,
    const __nv_bfloat16* Wh1, const __nv_bfloat16* Wl1, int C1,
    const __nv_bfloat16* Ah2, const __nv_bfloat16* Al2,
    const __nv_bfloat16* Wh2, const __nv_bfloat16* Wl2, int C2)
{
    const __nv_bfloat16 *Ah, *Al, *Wh, *Wl; size_t ao, wo;
    if (s < C1) {
        Ah = Ah1; Al = Al1; Wh = Wh1; Wl = Wl1;
        ao = ((size_t)(mt * C1 + s)) << 13;
        wo = ((size_t)(nt * C1 + s)) << 13;
    } else {
        const int c = s - C1;
        Ah = Ah2; Al = Al2; Wh = Wh2; Wl = Wl2;
        ao = ((size_t)(mt * C2 + c)) << 13;
        wo = ((size_t)(nt * C2 + c)) << 13;
    }
    const uint32_t d = sb + 1024 + buf * STG;
    const uint32_t m = sb + buf * 8;
    asm volatile("mbarrier.arrive.expect_tx.shared.b64 _, [%0], %1;"
                 :: "r"(m), "r"(65536u) : "memory");
    bulkcp(d,         Ah + ao, m);
    bulkcp(d + 16384, Al + ao, m);
    bulkcp(d + 32768, Wh + wo, m);
    bulkcp(d + 49152, Wl + wo, m);
}

__global__ __launch_bounds__(256) void tc_gemm(
    const __nv_bfloat16* __restrict__ Ah1, const __nv_bfloat16* __restrict__ Al1,
    const __nv_bfloat16* __restrict__ Wh1, const __nv_bfloat16* __restrict__ Wl1, int K1,
    const __nv_bfloat16* __restrict__ Ah2, const __nv_bfloat16* __restrict__ Al2,
    const __nv_bfloat16* __restrict__ Wh2, const __nv_bfloat16* __restrict__ Wl2, int K2,
    const float* __restrict__ bias, float* __restrict__ C, int Ntot)
{
    extern __shared__ char smem[];
    const uint32_t sb = smem_u32(smem);
    const int tid = threadIdx.x;
    const int wid = tid >> 5, lane = tid & 31;
    const int wm = wid & 1, wn = wid >> 1;
    const int mt = blockIdx.y, nt = blockIdx.x;
    const int m0 = mt * 128, n0 = nt * 128;
    const int C1 = K1 >> 6, C2 = K2 >> 6;
    const int S = C1 + C2;

    if (tid == 0) {
        MBARRIER_INIT(sb, 1);
        MBARRIER_INIT(sb + 8, 1);
        MBARRIER_INIT(sb + 16, 1);
    }
    __syncthreads();
    if (tid == 0) {
        issue_stage(0, 0, sb, mt, nt, Ah1, Al1, Wh1, Wl1, C1, Ah2, Al2, Wh2, Wl2, C2);
        if (S > 1) issue_stage(1, 1, sb, mt, nt, Ah1, Al1, Wh1, Wl1, C1, Ah2, Al2, Wh2, Wl2, C2);
        if (S > 2) issue_stage(2, 2, sb, mt, nt, Ah1, Al1, Wh1, Wl1, C1, Ah2, Al2, Wh2, Wl2, C2);
    }

    float acc[4][4][4];
    #pragma unroll
    for (int i = 0; i < 4; ++i)
        #pragma unroll
        for (int j = 0; j < 4; ++j)
            #pragma unroll
            for (int k = 0; k < 4; ++k) acc[i][j][k] = 0.f;

    const int tsel = lane >> 3;
    const int trow = lane & 7;
    int ph[3] = {0, 0, 0};

    for (int s = 0; s < S; ++s) {
        const int buf = s % 3;
        MBAR_WAIT(sb + buf * 8, ph[buf]);
        ph[buf] ^= 1;
        const uint32_t Ab  = sb + 1024 + buf * STG;
        const uint32_t Alb = Ab + 16384;
        const uint32_t Wb  = Ab + 32768;
        const uint32_t Wlb = Ab + 49152;

        #pragma unroll
        for (int ks = 0; ks < 4; ++ks) {
            uint32_t ah[4][4], al[4][4], bh[2][4], bl[2][4];
            #pragma unroll
            for (int mi = 0; mi < 4; ++mi) {
                const int row = wm * 64 + mi * 16 + (tsel & 1) * 8 + trow;
                const uint32_t off = row * 128 +
                    (uint32_t)((((ks * 2 + (tsel >> 1)) ^ (row & 7)) << 4));
                ldsm_x4(ah[mi], Ab + off);
                ldsm_x4(al[mi], Alb + off);
            }
            #pragma unroll
            for (int np = 0; np < 2; ++np) {
                const int n = wn * 32 + np * 16 + (tsel >> 1) * 8 + trow;
                const uint32_t off = n * 128 +
                    (uint32_t)((((ks * 2 + (tsel & 1)) ^ (n & 7)) << 4));
                ldsm_x4(bh[np], Wb + off);
                ldsm_x4(bl[np], Wlb + off);
            }
            #pragma unroll
            for (int mi = 0; mi < 4; ++mi)
                #pragma unroll
                for (int ni = 0; ni < 4; ++ni) {
                    const uint32_t h0 = bh[ni >> 1][(ni & 1) * 2];
                    const uint32_t h1 = bh[ni >> 1][(ni & 1) * 2 + 1];
                    const uint32_t l0 = bl[ni >> 1][(ni & 1) * 2];
                    const uint32_t l1 = bl[ni >> 1][(ni & 1) * 2 + 1];
                    mma_bf16(acc[mi][ni], ah[mi], h0, h1);
                    mma_bf16(acc[mi][ni], al[mi], h0, h1);
                    mma_bf16(acc[mi][ni], ah[mi], l0, l1);
                }
        }
        __syncthreads();
        if (tid == 0 && s + 3 < S)
            issue_stage(s + 3, buf, sb, mt, nt, Ah1, Al1, Wh1, Wl1, C1, Ah2, Al2, Wh2, Wl2, C2);
    }

    // epilogue: direct float2 stores
    const int erow = lane >> 2;
    const int ecol = (lane & 3) * 2;
    #pragma unroll
    for (int mi = 0; mi < 4; ++mi) {
        const int r0 = m0 + wm * 64 + mi * 16 + erow;
        #pragma unroll
        for (int ni = 0; ni < 4; ++ni) {
            const int n = n0 + wn * 32 + ni * 8 + ecol;
            float b0 = 0.f, b1 = 0.f;
            if (bias) { b0 = bias[n]; b1 = bias[n + 1]; }
            float2 v0 = make_float2(acc[mi][ni][0] + b0, acc[mi][ni][1] + b1);
            float2 v1 = make_float2(acc[mi][ni][2] + b0, acc[mi][ni][3] + b1);
            *(float2*)(C + (size_t)r0 * Ntot + n)       = v0;
            *(float2*)(C + (size_t)(r0 + 8) * Ntot + n) = v1;
        }
    }
}

// ===================== host driver ==========================================
extern "C" void kernel_launch(void* const* d_in, const int* in_sizes, int n_in,
                              void* d_out, int out_size) {
    int s = (in_sizes[3] <= 16) ? 0 : -1;

    const int*   input_var  = (const int*)  d_in[0];
    const float* input_mask = (const float*)d_in[1];
    const int*   target_var = (const int*)  d_in[2];
    const float* emb      = (const float*)d_in[4 + s];
    const float* attn_w   = (const float*)d_in[5 + s];
    const float* attn_b   = (const float*)d_in[6 + s];
    const float* set_Wih  = (const float*)d_in[7 + s];
    const float* set_Whh  = (const float*)d_in[8 + s];
    const float* set_bih  = (const float*)d_in[9 + s];
    const float* set_bhh  = (const float*)d_in[10 + s];
    const float* set_h0   = (const float*)d_in[11 + s];
    const float* set_c0   = (const float*)d_in[12 + s];
    const float* gen_x0   = (const float*)d_in[13 + s];
    const float* gen_Wih  = (const float*)d_in[14 + s];
    const float* gen_Whh  = (const float*)d_in[15 + s];
    const float* gen_bih  = (const float*)d_in[16 + s];
    const float* gen_bhh  = (const float*)d_in[17 + s];
    const float* gen_outW = (const float*)d_in[18 + s];
    const float* gen_outb = (const float*)d_in[19 + s];
    const float* menc_Wih = (const float*)d_in[20 + s];
    const float* menc_Whh = (const float*)d_in[21 + s];
    const float* menc_bih = (const float*)d_in[22 + s];
    const float* menc_bhh = (const float*)d_in[23 + s];
    const float* menc_h0  = (const float*)d_in[24 + s];
    const float* menc_c0  = (const float*)d_in[25 + s];
    const float* dec_Wih  = (const float*)d_in[26 + s];
    const float* dec_Whh  = (const float*)d_in[27 + s];
    const float* dec_bih  = (const float*)d_in[28 + s];
    const float* dec_bhh  = (const float*)d_in[29 + s];
    const float* dec_outW = (const float*)d_in[30 + s];
    const float* dec_outb = (const float*)d_in[31 + s];
    float* out = (float*)d_out;

    cudaFuncSetAttribute(tc_gemm, cudaFuncAttributeMaxDynamicSharedMemorySize, TC_SMEM_BYTES);

    float *p_g, *p_hb, *p_xb, *p_s0, *p_mmask;
    cudaGetSymbolAddress((void**)&p_g,     g_g);
    cudaGetSymbolAddress((void**)&p_hb,    g_hb_enc);
    cudaGetSymbolAddress((void**)&p_xb,    g_xb_gen);
    cudaGetSymbolAddress((void**)&p_s0,    g_s0);
    cudaGetSymbolAddress((void**)&p_mmask, g_mmask);

    __nv_bfloat16 *hh, *hl, *rh, *rl, *mh, *ml, *dh, *dl;
    cudaGetSymbolAddress((void**)&hh, g_h_hi);  cudaGetSymbolAddress((void**)&hl, g_h_lo);
    cudaGetSymbolAddress((void**)&rh, g_r_hi);  cudaGetSymbolAddress((void**)&rl, g_r_lo);
    cudaGetSymbolAddress((void**)&mh, g_msg_hi); cudaGetSymbolAddress((void**)&ml, g_msg_lo);
    cudaGetSymbolAddress((void**)&dh, g_din_hi); cudaGetSymbolAddress((void**)&dl, g_din_lo);

    __nv_bfloat16 *sWih_h, *sWih_l, *gWhh_h, *gWhh_l, *mWih_h, *mWih_l,
                  *mWhh_h, *mWhh_l, *dWih_h, *dWih_l, *dWhh_h, *dWhh_l, *oW_h, *oW_l;
    cudaGetSymbolAddress((void**)&sWih_h, w_setWih_hi);  cudaGetSymbolAddress((void**)&sWih_l, w_setWih_lo);
    cudaGetSymbolAddress((void**)&gWhh_h, w_genWhh_hi);  cudaGetSymbolAddress((void**)&gWhh_l, w_genWhh_lo);
    cudaGetSymbolAddress((void**)&mWih_h, w_mencWih_hi); cudaGetSymbolAddress((void**)&mWih_l, w_mencWih_lo);
    cudaGetSymbolAddress((void**)&mWhh_h, w_mencWhh_hi); cudaGetSymbolAddress((void**)&mWhh_l, w_mencWhh_lo);
    cudaGetSymbolAddress((void**)&dWih_h, w_decWih_hi);  cudaGetSymbolAddress((void**)&dWih_l, w_decWih_lo);
    cudaGetSymbolAddress((void**)&dWhh_h, w_decWhh_hi);  cudaGetSymbolAddress((void**)&dWhh_l, w_decWhh_lo);
    cudaGetSymbolAddress((void**)&oW_h,   w_outW_hi);    cudaGetSymbolAddress((void**)&oW_l,   w_outW_lo);

    const dim3 gBig(H4z / 128, Bz / 128);   // (32, 4)
    const dim3 gOut(Vz / 128,  Bz / 128);   // (8, 4)
    const int GATE_B = (Bz * Hz + 255) / 256;
    const int SPLIT_T = 256;

    // ---- weight splits into blocked layout ----
    split_w_blk_kernel<<<(H4z * Hz + SPLIT_T - 1) / SPLIT_T, SPLIT_T>>>(set_Wih,  sWih_h, sWih_l, Hz,  H4z * Hz);
    split_w_blk_kernel<<<(H4z * Hz + SPLIT_T - 1) / SPLIT_T, SPLIT_T>>>(gen_Whh,  gWhh_h, gWhh_l, Hz,  H4z * Hz);
    split_w_blk_kernel<<<(H4z * MVz + SPLIT_T - 1) / SPLIT_T, SPLIT_T>>>(menc_Wih, mWih_h, mWih_l, MVz, H4z * MVz);
    split_w_blk_kernel<<<(H4z * Hz + SPLIT_T - 1) / SPLIT_T, SPLIT_T>>>(menc_Whh, mWhh_h, mWhh_l, Hz,  H4z * Hz);
    split_w_blk_kernel<<<(H4z * Hz + SPLIT_T - 1) / SPLIT_T, SPLIT_T>>>(dec_Wih,  dWih_h, dWih_l, Hz,  H4z * Hz);
    split_w_blk_kernel<<<(H4z * Hz + SPLIT_T - 1) / SPLIT_T, SPLIT_T>>>(dec_Whh,  dWhh_h, dWhh_l, Hz,  H4z * Hz);
    split_w_blk_kernel<<<(Vz * Hz + SPLIT_T - 1) / SPLIT_T, SPLIT_T>>>(dec_outW, oW_h, oW_l, Hz, Vz * Hz);

    // ---- precompute ----
    vecmat_kernel<<<1, 32>>>(set_h0, attn_w, p_s0, 1, Hz);
    vecmat_kernel<<<H4z / 8, 256>>>(set_h0, set_Whh, p_hb, H4z, Hz);
    vecmat_kernel<<<H4z / 8, 256>>>(gen_x0, gen_Wih, p_xb, H4z, MVz);
    attn_aw_kernel<<<(Bz * Wz + 7) / 8, 256>>>(input_var, input_mask, emb, attn_w, attn_b);
    attn_r_kernel<<<Bz, 256>>>(input_var, emb);
    dec_gather_kernel<<<(int)(((size_t)Tz * Bz * Hz + 255) / 256), 256>>>(target_var, emb);
    init_m_kernel<<<2, 256>>>();

    // ---- set encoder ----
    bcast_BH_kernel<<<GATE_B, 256>>>(set_h0, 0);
    bcast_BH_kernel<<<GATE_B, 256>>>(set_c0, 1);
    tc_gemm<<<gBig, 256, TC_SMEM_BYTES>>>(rh, rl, sWih_h, sWih_l, Hz,
                                          nullptr, nullptr, nullptr, nullptr, 0,
                                          nullptr, p_g, H4z);
    lstm_gate_kernel<<<GATE_B, 256>>>(set_bih, set_bhh, p_hb, nullptr);

    // ---- generator loop ----
    for (int t = 0; t < Lz; ++t) {
        tc_gemm<<<gBig, 256, TC_SMEM_BYTES>>>(hh, hl, gWhh_h, gWhh_l, Hz,
                                              nullptr, nullptr, nullptr, nullptr, 0,
                                              nullptr, p_g, H4z);
        lstm_gate_kernel<<<GATE_B, 256>>>(gen_bih, gen_bhh, p_xb, nullptr);
        gen_out_kernel<<<Bz, 256>>>(gen_outW, gen_outb, t);
    }

    // ---- message encoder loop ----
    bcast_BH_kernel<<<GATE_B, 256>>>(menc_h0, 0);
    bcast_BH_kernel<<<GATE_B, 256>>>(menc_c0, 1);
    for (int t = 0; t < Lz; ++t) {
        tc_gemm<<<gBig, 256, TC_SMEM_BYTES>>>(mh + (size_t)t * Bz * MVz, ml + (size_t)t * Bz * MVz,
                                              mWih_h, mWih_l, MVz,
                                              hh, hl, mWhh_h, mWhh_l, Hz,
                                              nullptr, p_g, H4z);
        lstm_gate_kernel<<<GATE_B, 256>>>(menc_bih, menc_bhh, nullptr, p_mmask + (size_t)t * Bz);
    }

    // ---- decoder loop ----
    for (int t = 0; t < Tz; ++t) {
        tc_gemm<<<gBig, 256, TC_SMEM_BYTES>>>(dh + (size_t)t * Bz * Hz, dl + (size_t)t * Bz * Hz,
                                              dWih_h, dWih_l, Hz,
                                              hh, hl, dWhh_h, dWhh_l, Hz,
                                              nullptr, p_g, H4z);
        lstm_gate_kernel<<<GATE_B, 256>>>(dec_bih, dec_bhh, nullptr, nullptr);
        tc_gemm<<<gOut, 256, TC_SMEM_BYTES>>>(hh, hl, oW_h, oW_l, Hz,
                                              nullptr, nullptr, nullptr, nullptr, 0,
                                              dec_outb, out + (size_t)t * Bz * Vz, Vz);
    }
    (void)n_in; (void)out_size;
}